// round 1
// baseline (speedup 1.0000x reference)
#include <cuda_runtime.h>
#include <cuda_bf16.h>
#include <math.h>

// Problem constants
#define L      2048
#define DIM    4096
#define NH     32
#define NKV    8
#define HD     128
#define QDIM   (NH*HD)    // 4096
#define KVDIM  (NKV*HD)   // 1024
#define ATT_SCALE 0.08838834764831845f  // 128^-0.5

// Scratch (allocation-free rule: __device__ globals)
__device__ float g_q[L*QDIM];      // 32 MB
__device__ float g_k[L*KVDIM];     // 8 MB
__device__ float g_v[L*KVDIM];     // 8 MB
__device__ float g_attn[L*QDIM];   // 32 MB

// ---------------------------------------------------------------------------
// SGEMM: C[M,N] = A[M,K] @ B[K,N], all row-major fp32.
// 128x128 block, BK=8, 256 threads, 8x8 per thread.
// ---------------------------------------------------------------------------
#define BM 128
#define BN 128
#define BK 8
#define TM 8
#define TN 8

__global__ __launch_bounds__(256) void sgemm128(
    const float* __restrict__ A, const float* __restrict__ B,
    float* __restrict__ C, int M, int N, int K)
{
    __shared__ float As[BK][BM];
    __shared__ float Bs[BK][BN];
    const int bx = blockIdx.x;      // N tile
    const int by = blockIdx.y;      // M tile
    const int tid = threadIdx.x;
    const int tr = tid / 16;        // 0..15
    const int tc = tid % 16;        // 0..15

    const float* Ablk = A + (size_t)by * BM * K;
    const float* Bblk = B + (size_t)bx * BN;

    // loader mapping
    const int aRow  = tid >> 1;          // 0..127
    const int aCol4 = (tid & 1) * 4;     // 0 or 4
    const int bRow  = tid >> 5;          // 0..7
    const int bCol4 = (tid & 31) * 4;    // 0..124

    float acc[TM][TN] = {};

    for (int k0 = 0; k0 < K; k0 += BK) {
        float4 av = *(const float4*)(Ablk + (size_t)aRow * K + k0 + aCol4);
        As[aCol4 + 0][aRow] = av.x;
        As[aCol4 + 1][aRow] = av.y;
        As[aCol4 + 2][aRow] = av.z;
        As[aCol4 + 3][aRow] = av.w;
        float4 bv = *(const float4*)(Bblk + (size_t)(k0 + bRow) * N + bCol4);
        *(float4*)&Bs[bRow][bCol4] = bv;
        __syncthreads();

        #pragma unroll
        for (int kk = 0; kk < BK; kk++) {
            float ra[TM], rb[TN];
            *(float4*)&ra[0] = *(const float4*)&As[kk][tr * TM];
            *(float4*)&ra[4] = *(const float4*)&As[kk][tr * TM + 4];
            *(float4*)&rb[0] = *(const float4*)&Bs[kk][tc * TN];
            *(float4*)&rb[4] = *(const float4*)&Bs[kk][tc * TN + 4];
            #pragma unroll
            for (int i = 0; i < TM; i++)
                #pragma unroll
                for (int j = 0; j < TN; j++)
                    acc[i][j] += ra[i] * rb[j];
        }
        __syncthreads();
    }

    float* Cblk = C + (size_t)(by * BM) * N + (size_t)bx * BN;
    #pragma unroll
    for (int i = 0; i < TM; i++) {
        float* crow = Cblk + (size_t)(tr * TM + i) * N + tc * TN;
        *(float4*)(crow + 0) = make_float4(acc[i][0], acc[i][1], acc[i][2], acc[i][3]);
        *(float4*)(crow + 4) = make_float4(acc[i][4], acc[i][5], acc[i][6], acc[i][7]);
    }
}

// ---------------------------------------------------------------------------
// RoPE (reference's hybrid: interleaved rotation, concat-layout cos/sin index)
// x layout: [L, nheads, 128]. angle(j) = t * theta^(-(j mod 64)/64)
// out[2i]   = x[2i]  *cos(a(2i))   - x[2i+1]*sin(a(2i))
// out[2i+1] = x[2i+1]*cos(a(2i+1)) + x[2i]  *sin(a(2i+1))
// ---------------------------------------------------------------------------
__global__ void rope_kernel(float* __restrict__ x, int nheads, long total_pairs)
{
    long idx = (long)blockIdx.x * blockDim.x + threadIdx.x;
    if (idx >= total_pairs) return;
    int  p  = (int)(idx & 63);     // pair index in head dim (0..63)
    long th = idx >> 6;            // t*nheads + h
    int  t  = (int)(th / nheads);

    const float C = 0.14391156644565413f; // ln(10000)/64
    int j0 = 2 * p, j1 = 2 * p + 1;
    int m0 = j0 & 63, m1 = j1 & 63;
    float a0 = (float)t * expf(-C * (float)m0);
    float a1 = (float)t * expf(-C * (float)m1);
    float c0, s0, c1, s1;
    sincosf(a0, &s0, &c0);
    sincosf(a1, &s1, &c1);

    float* base = x + th * 128;
    float x0 = base[j0];
    float x1 = base[j1];
    base[j0] = x0 * c0 - x1 * s0;
    base[j1] = x1 * c1 + x0 * s1;
}

// ---------------------------------------------------------------------------
// Write repeated (roped) K and repeated V into the output's k/v sections.
// out layout: [NH, L, HD]; source: [L, NKV, HD]
// ---------------------------------------------------------------------------
__global__ void write_kv_kernel(const float* __restrict__ k,
                                const float* __restrict__ v,
                                float* __restrict__ ok, float* __restrict__ ov)
{
    long idx = (long)blockIdx.x * blockDim.x + threadIdx.x;
    const long total = (long)NH * L * HD;
    if (idx >= total) return;
    int h = (int)(idx >> 18);           // / (2048*128)
    int rem = (int)(idx & 262143);
    int t = rem >> 7;
    int d = rem & 127;
    int src = t * KVDIM + (h >> 2) * HD + d;
    ok[idx] = k[src];
    ov[idx] = v[src];
}

// ---------------------------------------------------------------------------
// Flash attention, non-causal full softmax.
// Block: one head (grid.y) x one 64-row Q tile (grid.x). 256 threads.
// S tile 64x64 via register tiling; streaming softmax; PV accumulate.
// ---------------------------------------------------------------------------
#define AT_BM 64
#define AT_BN 64
#define QT_STRIDE 68   // padded, 16B-aligned stride for d-major Q/K tiles

__global__ __launch_bounds__(256) void attn_kernel(
    const float* __restrict__ q, const float* __restrict__ k,
    const float* __restrict__ v, float* __restrict__ o)
{
    extern __shared__ float sm[];
    float* Qt  = sm;                       // [128][QT_STRIDE], d-major
    float* Kt  = Qt + 128 * QT_STRIDE;     // [128][QT_STRIDE], d-major
    float* Vs  = Kt + 128 * QT_STRIDE;     // [64][128]
    float* S   = Vs + 64 * 128;            // [64][QT_STRIDE]
    float* rowm = S + 64 * QT_STRIDE;      // [64]
    float* rowl = rowm + 64;               // [64]
    float* rowf = rowl + 64;               // [64]

    const int h   = blockIdx.y;
    const int qt  = blockIdx.x;
    const int kvh = h >> 2;
    const int tid = threadIdx.x;
    const int tr  = tid >> 4;      // 0..15
    const int tc  = tid & 15;      // 0..15
    const int r0  = tr * 4;        // owned rows (both phases)
    const int c0  = tc * 4;        // S cols
    const int oc0 = tc * 8;        // O cols

    // Load Q tile (64x128) transposed to d-major
    for (int i = tid; i < 64 * 32; i += 256) {
        int r = i >> 5, c4 = (i & 31) * 4;
        float4 val = *(const float4*)(q + (size_t)(qt * 64 + r) * QDIM + h * HD + c4);
        Qt[(c4 + 0) * QT_STRIDE + r] = val.x;
        Qt[(c4 + 1) * QT_STRIDE + r] = val.y;
        Qt[(c4 + 2) * QT_STRIDE + r] = val.z;
        Qt[(c4 + 3) * QT_STRIDE + r] = val.w;
    }
    if (tid < 64) { rowm[tid] = -1e30f; rowl[tid] = 0.f; }
    __syncthreads();

    float o_acc[4][8] = {};

    for (int kt = 0; kt < L / AT_BN; kt++) {
        // Load K (transposed) and V tiles
        for (int i = tid; i < 64 * 32; i += 256) {
            int r = i >> 5, c4 = (i & 31) * 4;
            size_t gsrc = (size_t)(kt * 64 + r) * KVDIM + kvh * HD + c4;
            float4 kv4 = *(const float4*)(k + gsrc);
            Kt[(c4 + 0) * QT_STRIDE + r] = kv4.x;
            Kt[(c4 + 1) * QT_STRIDE + r] = kv4.y;
            Kt[(c4 + 2) * QT_STRIDE + r] = kv4.z;
            Kt[(c4 + 3) * QT_STRIDE + r] = kv4.w;
            *(float4*)&Vs[r * 128 + c4] = *(const float4*)(v + gsrc);
        }
        __syncthreads();

        // S = Q @ K^T (4x4 per thread)
        float acc[4][4] = {};
        #pragma unroll 4
        for (int d = 0; d < 128; d++) {
            float4 ra = *(const float4*)&Qt[d * QT_STRIDE + r0];
            float4 rb = *(const float4*)&Kt[d * QT_STRIDE + c0];
            acc[0][0] += ra.x * rb.x; acc[0][1] += ra.x * rb.y; acc[0][2] += ra.x * rb.z; acc[0][3] += ra.x * rb.w;
            acc[1][0] += ra.y * rb.x; acc[1][1] += ra.y * rb.y; acc[1][2] += ra.y * rb.z; acc[1][3] += ra.y * rb.w;
            acc[2][0] += ra.z * rb.x; acc[2][1] += ra.z * rb.y; acc[2][2] += ra.z * rb.z; acc[2][3] += ra.z * rb.w;
            acc[3][0] += ra.w * rb.x; acc[3][1] += ra.w * rb.y; acc[3][2] += ra.w * rb.z; acc[3][3] += ra.w * rb.w;
        }
        #pragma unroll
        for (int i = 0; i < 4; i++)
            #pragma unroll
            for (int j = 0; j < 4; j++)
                S[(r0 + i) * QT_STRIDE + c0 + j] = acc[i][j] * ATT_SCALE;
        __syncthreads();

        // Streaming softmax row pass (one thread per row)
        if (tid < 64) {
            int r = tid;
            float m_old = rowm[r];
            float mx = m_old;
            #pragma unroll 8
            for (int j = 0; j < 64; j++) mx = fmaxf(mx, S[r * QT_STRIDE + j]);
            float fct = __expf(m_old - mx);
            float srow = 0.f;
            #pragma unroll 8
            for (int j = 0; j < 64; j++) {
                float pexp = __expf(S[r * QT_STRIDE + j] - mx);
                S[r * QT_STRIDE + j] = pexp;
                srow += pexp;
            }
            rowm[r] = mx;
            rowl[r] = rowl[r] * fct + srow;
            rowf[r] = fct;
        }
        __syncthreads();

        // Rescale O, accumulate P @ V
        float f0 = rowf[r0], f1 = rowf[r0 + 1], f2 = rowf[r0 + 2], f3 = rowf[r0 + 3];
        #pragma unroll
        for (int j = 0; j < 8; j++) {
            o_acc[0][j] *= f0; o_acc[1][j] *= f1; o_acc[2][j] *= f2; o_acc[3][j] *= f3;
        }
        #pragma unroll 2
        for (int kk = 0; kk < 64; kk++) {
            float p0 = S[(r0 + 0) * QT_STRIDE + kk];
            float p1 = S[(r0 + 1) * QT_STRIDE + kk];
            float p2 = S[(r0 + 2) * QT_STRIDE + kk];
            float p3 = S[(r0 + 3) * QT_STRIDE + kk];
            float4 va = *(const float4*)&Vs[kk * 128 + oc0];
            float4 vb = *(const float4*)&Vs[kk * 128 + oc0 + 4];
            float vv[8] = {va.x, va.y, va.z, va.w, vb.x, vb.y, vb.z, vb.w};
            #pragma unroll
            for (int j = 0; j < 8; j++) {
                o_acc[0][j] += p0 * vv[j];
                o_acc[1][j] += p1 * vv[j];
                o_acc[2][j] += p2 * vv[j];
                o_acc[3][j] += p3 * vv[j];
            }
        }
        __syncthreads();
    }

    // Epilogue: normalize and write to [L, NH*HD] scratch
    #pragma unroll
    for (int i = 0; i < 4; i++) {
        float inv = 1.f / rowl[r0 + i];
        float* dst = o + (size_t)(qt * 64 + r0 + i) * QDIM + h * HD + oc0;
        float4 w0 = make_float4(o_acc[i][0] * inv, o_acc[i][1] * inv, o_acc[i][2] * inv, o_acc[i][3] * inv);
        float4 w1 = make_float4(o_acc[i][4] * inv, o_acc[i][5] * inv, o_acc[i][6] * inv, o_acc[i][7] * inv);
        *(float4*)(dst + 0) = w0;
        *(float4*)(dst + 4) = w1;
    }
}

// ---------------------------------------------------------------------------
// Launch
// ---------------------------------------------------------------------------
extern "C" void kernel_launch(void* const* d_in, const int* in_sizes, int n_in,
                              void* d_out, int out_size)
{
    const float* x  = (const float*)d_in[0];
    const float* wq = (const float*)d_in[1];
    const float* wk = (const float*)d_in[2];
    const float* wv = (const float*)d_in[3];
    const float* wo = (const float*)d_in[4];
    float* out = (float*)d_out;

    float *pq, *pk, *pv, *pattn;
    cudaGetSymbolAddress((void**)&pq, g_q);
    cudaGetSymbolAddress((void**)&pk, g_k);
    cudaGetSymbolAddress((void**)&pv, g_v);
    cudaGetSymbolAddress((void**)&pattn, g_attn);

    // QKV projections
    sgemm128<<<dim3(QDIM / BN, L / BM), 256>>>(x, wq, pq, L, QDIM, DIM);
    sgemm128<<<dim3(KVDIM / BN, L / BM), 256>>>(x, wk, pk, L, KVDIM, DIM);
    sgemm128<<<dim3(KVDIM / BN, L / BM), 256>>>(x, wv, pv, L, KVDIM, DIM);

    // RoPE on q and k
    {
        long pq_pairs = (long)L * NH * 64;
        long pk_pairs = (long)L * NKV * 64;
        rope_kernel<<<(unsigned)((pq_pairs + 255) / 256), 256>>>(pq, NH, pq_pairs);
        rope_kernel<<<(unsigned)((pk_pairs + 255) / 256), 256>>>(pk, NKV, pk_pairs);
    }

    // Emit repeated (k, v) output sections if the output buffer carries them
    const long OUT0 = (long)L * QDIM;          // 8388608
    const long KVSZ = (long)NH * L * HD;       // 8388608
    if ((long)out_size >= OUT0 + 2 * KVSZ) {
        long total = KVSZ;
        write_kv_kernel<<<(unsigned)((total + 255) / 256), 256>>>(
            pk, pv, out + OUT0, out + OUT0 + KVSZ);
    }

    // Flash attention
    {
        size_t smem = (size_t)(128 * QT_STRIDE * 2 + 64 * 128 + 64 * QT_STRIDE + 3 * 64) * sizeof(float);
        cudaFuncSetAttribute(attn_kernel, cudaFuncAttributeMaxDynamicSharedMemorySize, (int)smem);
        attn_kernel<<<dim3(L / AT_BM, NH), 256, smem>>>(pq, pk, pv, pattn);
    }

    // Output projection
    sgemm128<<<dim3(DIM / BN, L / BM), 256>>>(pattn, wo, out, L, DIM, DIM);
}

// round 2
// speedup vs baseline: 1.8061x; 1.8061x over previous
#include <cuda_runtime.h>
#include <cuda_bf16.h>
#include <math.h>

// Problem constants
#define L      2048
#define DIM    4096
#define NH     32
#define NKV    8
#define HD     128
#define QDIM   (NH*HD)    // 4096
#define KVDIM  (NKV*HD)   // 1024
#define ATT_SCALE 0.08838834764831845f  // 128^-0.5

// Scratch (allocation-free rule: __device__ globals)
__device__ float g_q[L*QDIM];      // 32 MB
__device__ float g_k[L*KVDIM];     // 8 MB
__device__ float g_v[L*KVDIM];     // 8 MB
__device__ float g_attn[L*QDIM];   // 32 MB

// ---------------------------------------------------------------------------
// tf32 helpers
// ---------------------------------------------------------------------------
__device__ __forceinline__ unsigned f2tf32(float f) {
    unsigned u;
    asm("cvt.rna.tf32.f32 %0, %1;" : "=r"(u) : "f"(f));
    return u;
}

__device__ __forceinline__ void mma_tf32(float c[4], const unsigned a[4], const unsigned b[2]) {
    asm volatile(
        "mma.sync.aligned.m16n8k8.row.col.f32.tf32.tf32.f32 "
        "{%0,%1,%2,%3},{%4,%5,%6,%7},{%8,%9},{%0,%1,%2,%3};"
        : "+f"(c[0]), "+f"(c[1]), "+f"(c[2]), "+f"(c[3])
        : "r"(a[0]), "r"(a[1]), "r"(a[2]), "r"(a[3]), "r"(b[0]), "r"(b[1]));
}

__device__ __forceinline__ void cp16(void* smem, const void* g) {
    unsigned s = (unsigned)__cvta_generic_to_shared(smem);
    asm volatile("cp.async.cg.shared.global [%0], [%1], 16;" :: "r"(s), "l"(g));
}
#define CP_COMMIT()  asm volatile("cp.async.commit_group;")
#define CP_WAIT(n)   asm volatile("cp.async.wait_group %0;" :: "n"(n))

// ---------------------------------------------------------------------------
// Tensor-core tf32 GEMM: C[M,N] = A[M,K] @ B[K,N], row-major fp32.
// 128x128x32 block tiles, 8 warps (2x4), warp tile 64x32, m16n8k8 fragments.
// 2-stage cp.async pipeline. Requires M%128==0, N%128==0, K%32==0.
// ---------------------------------------------------------------------------
#define AS_STRIDE 36    // 32 + 4 pad -> bank-conflict-free fragment LDS
#define BS_STRIDE 132   // 128 + 4 pad
#define AS_TILE  (128*AS_STRIDE)
#define BS_TILE  (32*BS_STRIDE)

__global__ __launch_bounds__(256) void gemm_tf32(
    const float* __restrict__ A, const float* __restrict__ B,
    float* __restrict__ C, int M, int N, int K)
{
    extern __shared__ float sm[];
    float* As = sm;                 // [2][128][36]
    float* Bs = sm + 2 * AS_TILE;   // [2][32][132]

    const int tid  = threadIdx.x;
    const int lane = tid & 31;
    const int wid  = tid >> 5;
    const int wm   = (wid & 1) * 64;
    const int wn   = (wid >> 1) * 32;
    const int lr   = lane >> 2;     // 0..7
    const int lc   = lane & 3;      // 0..3
    const int bx   = blockIdx.x;
    const int by   = blockIdx.y;

    const float* Ag = A + (size_t)by * 128 * K;
    const float* Bg = B + (size_t)bx * 128;

    const int arow = tid >> 3;          // 0..31 (+32 steps)
    const int acol = (tid & 7) * 4;     // 0..28
    const int brow = tid >> 5;          // 0..7  (+8 steps)
    const int bcol = (tid & 31) * 4;    // 0..124

    float acc[4][4][4] = {};            // [mi][ni][reg]

    const int nit = K / 32;

    // prologue: stage 0
    #pragma unroll
    for (int r = 0; r < 4; r++)
        cp16(&As[(arow + r*32)*AS_STRIDE + acol], Ag + (size_t)(arow + r*32) * K + acol);
    #pragma unroll
    for (int r = 0; r < 4; r++)
        cp16(&Bs[(brow + r*8)*BS_STRIDE + bcol], Bg + (size_t)(brow + r*8) * N + bcol);
    CP_COMMIT();

    for (int it = 0; it < nit; it++) {
        const int cur = it & 1;
        if (it + 1 < nit) {
            const int nxt = cur ^ 1;
            const int k0 = (it + 1) * 32;
            #pragma unroll
            for (int r = 0; r < 4; r++)
                cp16(&As[nxt*AS_TILE + (arow + r*32)*AS_STRIDE + acol],
                     Ag + (size_t)(arow + r*32) * K + k0 + acol);
            #pragma unroll
            for (int r = 0; r < 4; r++)
                cp16(&Bs[nxt*BS_TILE + (brow + r*8)*BS_STRIDE + bcol],
                     Bg + (size_t)(k0 + brow + r*8) * N + bcol);
            CP_COMMIT();
            CP_WAIT(1);
        } else {
            CP_WAIT(0);
        }
        __syncthreads();

        const float* Ab = &As[cur * AS_TILE];
        const float* Bb = &Bs[cur * BS_TILE];

        #pragma unroll
        for (int ks = 0; ks < 4; ks++) {
            unsigned a[4][4], b[4][2];
            #pragma unroll
            for (int mi = 0; mi < 4; mi++) {
                const float* p = &Ab[(wm + mi*16 + lr) * AS_STRIDE + ks*8 + lc];
                a[mi][0] = f2tf32(p[0]);
                a[mi][1] = f2tf32(p[8 * AS_STRIDE]);
                a[mi][2] = f2tf32(p[4]);
                a[mi][3] = f2tf32(p[8 * AS_STRIDE + 4]);
            }
            #pragma unroll
            for (int ni = 0; ni < 4; ni++) {
                const float* p = &Bb[(ks*8 + lc) * BS_STRIDE + wn + ni*8 + lr];
                b[ni][0] = f2tf32(p[0]);
                b[ni][1] = f2tf32(p[4 * BS_STRIDE]);
            }
            #pragma unroll
            for (int mi = 0; mi < 4; mi++)
                #pragma unroll
                for (int ni = 0; ni < 4; ni++)
                    mma_tf32(acc[mi][ni], a[mi], b[ni]);
        }
        __syncthreads();
    }

    // Epilogue
    #pragma unroll
    for (int mi = 0; mi < 4; mi++) {
        #pragma unroll
        for (int ni = 0; ni < 4; ni++) {
            int row = by * 128 + wm + mi*16 + lr;
            int col = bx * 128 + wn + ni*8 + lc*2;
            *(float2*)&C[(size_t)row * N + col] =
                make_float2(acc[mi][ni][0], acc[mi][ni][1]);
            *(float2*)&C[(size_t)(row + 8) * N + col] =
                make_float2(acc[mi][ni][2], acc[mi][ni][3]);
        }
    }
}

// ---------------------------------------------------------------------------
// RoPE (reference's hybrid: interleaved rotation, concat-layout cos/sin index)
// ---------------------------------------------------------------------------
__global__ void rope_kernel(float* __restrict__ x, int nheads, long total_pairs)
{
    long idx = (long)blockIdx.x * blockDim.x + threadIdx.x;
    if (idx >= total_pairs) return;
    int  p  = (int)(idx & 63);
    long th = idx >> 6;
    int  t  = (int)(th / nheads);

    const float C = 0.14391156644565413f; // ln(10000)/64
    int j0 = 2 * p, j1 = 2 * p + 1;
    int m0 = j0 & 63, m1 = j1 & 63;
    float a0 = (float)t * expf(-C * (float)m0);
    float a1 = (float)t * expf(-C * (float)m1);
    float c0, s0, c1, s1;
    sincosf(a0, &s0, &c0);
    sincosf(a1, &s1, &c1);

    float* base = x + th * 128;
    float x0 = base[j0];
    float x1 = base[j1];
    base[j0] = x0 * c0 - x1 * s0;
    base[j1] = x1 * c1 + x0 * s1;
}

// ---------------------------------------------------------------------------
// Write repeated (roped) K and repeated V into the output's k/v sections.
// ---------------------------------------------------------------------------
__global__ void write_kv_kernel(const float* __restrict__ k,
                                const float* __restrict__ v,
                                float* __restrict__ ok, float* __restrict__ ov)
{
    long idx = (long)blockIdx.x * blockDim.x + threadIdx.x;
    const long total = (long)NH * L * HD;
    if (idx >= total) return;
    int h = (int)(idx >> 18);
    int rem = (int)(idx & 262143);
    int t = rem >> 7;
    int d = rem & 127;
    int src = t * KVDIM + (h >> 2) * HD + d;
    ok[idx] = k[src];
    ov[idx] = v[src];
}

// ---------------------------------------------------------------------------
// Flash attention, non-causal full softmax (SIMT, unchanged from R1).
// ---------------------------------------------------------------------------
#define AT_BM 64
#define AT_BN 64
#define QT_STRIDE 68

__global__ __launch_bounds__(256) void attn_kernel(
    const float* __restrict__ q, const float* __restrict__ k,
    const float* __restrict__ v, float* __restrict__ o)
{
    extern __shared__ float smA[];
    float* Qt  = smA;
    float* Kt  = Qt + 128 * QT_STRIDE;
    float* Vs  = Kt + 128 * QT_STRIDE;
    float* S   = Vs + 64 * 128;
    float* rowm = S + 64 * QT_STRIDE;
    float* rowl = rowm + 64;
    float* rowf = rowl + 64;

    const int h   = blockIdx.y;
    const int qt  = blockIdx.x;
    const int kvh = h >> 2;
    const int tid = threadIdx.x;
    const int tr  = tid >> 4;
    const int tc  = tid & 15;
    const int r0  = tr * 4;
    const int c0  = tc * 4;
    const int oc0 = tc * 8;

    for (int i = tid; i < 64 * 32; i += 256) {
        int r = i >> 5, c4 = (i & 31) * 4;
        float4 val = *(const float4*)(q + (size_t)(qt * 64 + r) * QDIM + h * HD + c4);
        Qt[(c4 + 0) * QT_STRIDE + r] = val.x;
        Qt[(c4 + 1) * QT_STRIDE + r] = val.y;
        Qt[(c4 + 2) * QT_STRIDE + r] = val.z;
        Qt[(c4 + 3) * QT_STRIDE + r] = val.w;
    }
    if (tid < 64) { rowm[tid] = -1e30f; rowl[tid] = 0.f; }
    __syncthreads();

    float o_acc[4][8] = {};

    for (int kt = 0; kt < L / AT_BN; kt++) {
        for (int i = tid; i < 64 * 32; i += 256) {
            int r = i >> 5, c4 = (i & 31) * 4;
            size_t gsrc = (size_t)(kt * 64 + r) * KVDIM + kvh * HD + c4;
            float4 kv4 = *(const float4*)(k + gsrc);
            Kt[(c4 + 0) * QT_STRIDE + r] = kv4.x;
            Kt[(c4 + 1) * QT_STRIDE + r] = kv4.y;
            Kt[(c4 + 2) * QT_STRIDE + r] = kv4.z;
            Kt[(c4 + 3) * QT_STRIDE + r] = kv4.w;
            *(float4*)&Vs[r * 128 + c4] = *(const float4*)(v + gsrc);
        }
        __syncthreads();

        float acc[4][4] = {};
        #pragma unroll 4
        for (int d = 0; d < 128; d++) {
            float4 ra = *(const float4*)&Qt[d * QT_STRIDE + r0];
            float4 rb = *(const float4*)&Kt[d * QT_STRIDE + c0];
            acc[0][0] += ra.x * rb.x; acc[0][1] += ra.x * rb.y; acc[0][2] += ra.x * rb.z; acc[0][3] += ra.x * rb.w;
            acc[1][0] += ra.y * rb.x; acc[1][1] += ra.y * rb.y; acc[1][2] += ra.y * rb.z; acc[1][3] += ra.y * rb.w;
            acc[2][0] += ra.z * rb.x; acc[2][1] += ra.z * rb.y; acc[2][2] += ra.z * rb.z; acc[2][3] += ra.z * rb.w;
            acc[3][0] += ra.w * rb.x; acc[3][1] += ra.w * rb.y; acc[3][2] += ra.w * rb.z; acc[3][3] += ra.w * rb.w;
        }
        #pragma unroll
        for (int i = 0; i < 4; i++)
            #pragma unroll
            for (int j = 0; j < 4; j++)
                S[(r0 + i) * QT_STRIDE + c0 + j] = acc[i][j] * ATT_SCALE;
        __syncthreads();

        if (tid < 64) {
            int r = tid;
            float m_old = rowm[r];
            float mx = m_old;
            #pragma unroll 8
            for (int j = 0; j < 64; j++) mx = fmaxf(mx, S[r * QT_STRIDE + j]);
            float fct = __expf(m_old - mx);
            float srow = 0.f;
            #pragma unroll 8
            for (int j = 0; j < 64; j++) {
                float pexp = __expf(S[r * QT_STRIDE + j] - mx);
                S[r * QT_STRIDE + j] = pexp;
                srow += pexp;
            }
            rowm[r] = mx;
            rowl[r] = rowl[r] * fct + srow;
            rowf[r] = fct;
        }
        __syncthreads();

        float f0 = rowf[r0], f1 = rowf[r0 + 1], f2 = rowf[r0 + 2], f3 = rowf[r0 + 3];
        #pragma unroll
        for (int j = 0; j < 8; j++) {
            o_acc[0][j] *= f0; o_acc[1][j] *= f1; o_acc[2][j] *= f2; o_acc[3][j] *= f3;
        }
        #pragma unroll 2
        for (int kk = 0; kk < 64; kk++) {
            float p0 = S[(r0 + 0) * QT_STRIDE + kk];
            float p1 = S[(r0 + 1) * QT_STRIDE + kk];
            float p2 = S[(r0 + 2) * QT_STRIDE + kk];
            float p3 = S[(r0 + 3) * QT_STRIDE + kk];
            float4 va = *(const float4*)&Vs[kk * 128 + oc0];
            float4 vb = *(const float4*)&Vs[kk * 128 + oc0 + 4];
            float vv[8] = {va.x, va.y, va.z, va.w, vb.x, vb.y, vb.z, vb.w};
            #pragma unroll
            for (int j = 0; j < 8; j++) {
                o_acc[0][j] += p0 * vv[j];
                o_acc[1][j] += p1 * vv[j];
                o_acc[2][j] += p2 * vv[j];
                o_acc[3][j] += p3 * vv[j];
            }
        }
        __syncthreads();
    }

    #pragma unroll
    for (int i = 0; i < 4; i++) {
        float inv = 1.f / rowl[r0 + i];
        float* dst = o + (size_t)(qt * 64 + r0 + i) * QDIM + h * HD + oc0;
        *(float4*)(dst + 0) = make_float4(o_acc[i][0] * inv, o_acc[i][1] * inv, o_acc[i][2] * inv, o_acc[i][3] * inv);
        *(float4*)(dst + 4) = make_float4(o_acc[i][4] * inv, o_acc[i][5] * inv, o_acc[i][6] * inv, o_acc[i][7] * inv);
    }
}

// ---------------------------------------------------------------------------
// Launch
// ---------------------------------------------------------------------------
extern "C" void kernel_launch(void* const* d_in, const int* in_sizes, int n_in,
                              void* d_out, int out_size)
{
    const float* x  = (const float*)d_in[0];
    const float* wq = (const float*)d_in[1];
    const float* wk = (const float*)d_in[2];
    const float* wv = (const float*)d_in[3];
    const float* wo = (const float*)d_in[4];
    float* out = (float*)d_out;

    float *pq, *pk, *pv, *pattn;
    cudaGetSymbolAddress((void**)&pq, g_q);
    cudaGetSymbolAddress((void**)&pk, g_k);
    cudaGetSymbolAddress((void**)&pv, g_v);
    cudaGetSymbolAddress((void**)&pattn, g_attn);

    const size_t gemm_smem = (size_t)(2 * AS_TILE + 2 * BS_TILE) * sizeof(float); // ~70.6 KB
    static int gemm_attr_set = 0;
    if (!gemm_attr_set) {
        cudaFuncSetAttribute(gemm_tf32, cudaFuncAttributeMaxDynamicSharedMemorySize, (int)gemm_smem);
        gemm_attr_set = 1;
    }

    // QKV projections (tensor cores, tf32)
    gemm_tf32<<<dim3(QDIM / 128, L / 128), 256, gemm_smem>>>(x, wq, pq, L, QDIM, DIM);
    gemm_tf32<<<dim3(KVDIM / 128, L / 128), 256, gemm_smem>>>(x, wk, pk, L, KVDIM, DIM);
    gemm_tf32<<<dim3(KVDIM / 128, L / 128), 256, gemm_smem>>>(x, wv, pv, L, KVDIM, DIM);

    // RoPE on q and k
    {
        long pq_pairs = (long)L * NH * 64;
        long pk_pairs = (long)L * NKV * 64;
        rope_kernel<<<(unsigned)((pq_pairs + 255) / 256), 256>>>(pq, NH, pq_pairs);
        rope_kernel<<<(unsigned)((pk_pairs + 255) / 256), 256>>>(pk, NKV, pk_pairs);
    }

    // Emit repeated (k, v) output sections if the output buffer carries them
    const long OUT0 = (long)L * QDIM;
    const long KVSZ = (long)NH * L * HD;
    if ((long)out_size >= OUT0 + 2 * KVSZ) {
        long total = KVSZ;
        write_kv_kernel<<<(unsigned)((total + 255) / 256), 256>>>(
            pk, pv, out + OUT0, out + OUT0 + KVSZ);
    }

    // Flash attention (SIMT)
    {
        size_t smem = (size_t)(128 * QT_STRIDE * 2 + 64 * 128 + 64 * QT_STRIDE + 3 * 64) * sizeof(float);
        cudaFuncSetAttribute(attn_kernel, cudaFuncAttributeMaxDynamicSharedMemorySize, (int)smem);
        attn_kernel<<<dim3(L / AT_BM, NH), 256, smem>>>(pq, pk, pv, pattn);
    }

    // Output projection (tensor cores, tf32)
    gemm_tf32<<<dim3(DIM / 128, L / 128), 256, gemm_smem>>>(pattn, wo, out, L, DIM, DIM);
}

// round 5
// speedup vs baseline: 3.5300x; 1.9544x over previous
#include <cuda_runtime.h>
#include <cuda_fp16.h>
#include <cuda_bf16.h>
#include <cstdint>
#include <math.h>

// Problem constants
#define L      2048
#define DIM    4096
#define NH     32
#define NKV    8
#define HD     128
#define QDIM   (NH*HD)    // 4096
#define KVDIM  (NKV*HD)   // 1024
#define ATT_SCALE 0.08838834764831845f  // 128^-0.5

// ---------------------------------------------------------------------------
// Scratch (__device__ globals; no allocations allowed)
// ---------------------------------------------------------------------------
__device__ float g_q[L*QDIM];                 // q fp32 (pre-rope)
__device__ float g_kv[L*2*KVDIM];             // [L][k(1024) | v(1024)] fp32
__device__ float g_attn[L*QDIM];              // attention output fp32
__device__ __half g_qh[L*QDIM];               // q fp16, roped, *ATT_SCALE
__device__ __half g_kh[L*KVDIM];              // k fp16, roped
__device__ __half g_vh[L*KVDIM];              // v fp16

__device__ __nv_bfloat16 g_xh[L*DIM],  g_xl[L*DIM];
__device__ __nv_bfloat16 g_ah[L*QDIM], g_al[L*QDIM];
__device__ __nv_bfloat16 g_wqh[DIM*QDIM],  g_wql[DIM*QDIM];      // [N=4096][K=4096]
__device__ __nv_bfloat16 g_kvh[2*KVDIM*DIM], g_kvl[2*KVDIM*DIM]; // [N=2048][K=4096]
__device__ __nv_bfloat16 g_woh[QDIM*DIM],  g_wol[QDIM*DIM];      // [N=4096][K=4096]

// ---------------------------------------------------------------------------
// sm_80-era PTX helpers (valid on base compute_103 target)
// ---------------------------------------------------------------------------
__device__ __forceinline__ uint32_t smem_u32(const void* p) {
    uint32_t a;
    asm("{ .reg .u64 t; cvta.to.shared.u64 t, %1; cvt.u32.u64 %0, t; }" : "=r"(a) : "l"(p));
    return a;
}
__device__ __forceinline__ void cp16(void* smem, const void* g) {
    uint32_t s = smem_u32(smem);
    asm volatile("cp.async.cg.shared.global [%0], [%1], 16;" :: "r"(s), "l"(g));
}
#define CP_COMMIT() asm volatile("cp.async.commit_group;")
#define CP_WAIT0()  asm volatile("cp.async.wait_group 0;")
#define CP_WAIT1()  asm volatile("cp.async.wait_group 1;")

__device__ __forceinline__ void ldsm4(uint32_t* r, uint32_t addr) {
    asm volatile("ldmatrix.sync.aligned.m8n8.x4.shared.b16 {%0,%1,%2,%3}, [%4];"
                 : "=r"(r[0]), "=r"(r[1]), "=r"(r[2]), "=r"(r[3]) : "r"(addr));
}
__device__ __forceinline__ void ldsm4t(uint32_t* r, uint32_t addr) {
    asm volatile("ldmatrix.sync.aligned.m8n8.x4.trans.shared.b16 {%0,%1,%2,%3}, [%4];"
                 : "=r"(r[0]), "=r"(r[1]), "=r"(r[2]), "=r"(r[3]) : "r"(addr));
}
__device__ __forceinline__ void mma_bf16(float* c, const uint32_t* a, const uint32_t* b) {
    asm volatile("mma.sync.aligned.m16n8k16.row.col.f32.bf16.bf16.f32 "
                 "{%0,%1,%2,%3},{%4,%5,%6,%7},{%8,%9},{%0,%1,%2,%3};"
                 : "+f"(c[0]), "+f"(c[1]), "+f"(c[2]), "+f"(c[3])
                 : "r"(a[0]), "r"(a[1]), "r"(a[2]), "r"(a[3]), "r"(b[0]), "r"(b[1]));
}
__device__ __forceinline__ void mma_f16(float* c, const uint32_t* a, const uint32_t* b) {
    asm volatile("mma.sync.aligned.m16n8k16.row.col.f32.f16.f16.f32 "
                 "{%0,%1,%2,%3},{%4,%5,%6,%7},{%8,%9},{%0,%1,%2,%3};"
                 : "+f"(c[0]), "+f"(c[1]), "+f"(c[2]), "+f"(c[3])
                 : "r"(a[0]), "r"(a[1]), "r"(a[2]), "r"(a[3]), "r"(b[0]), "r"(b[1]));
}
__device__ __forceinline__ uint32_t pack_h2(float lo, float hi) {
    uint32_t r;
    asm("cvt.rn.f16x2.f32 %0, %1, %2;" : "=r"(r) : "f"(hi), "f"(lo));
    return r;
}

// ---------------------------------------------------------------------------
// Split kernels: fp32 -> bf16 hi + lo
// ---------------------------------------------------------------------------
__global__ void split_kernel(const float* __restrict__ x,
                             __nv_bfloat16* __restrict__ h,
                             __nv_bfloat16* __restrict__ l, long n)
{
    long i = ((long)blockIdx.x * blockDim.x + threadIdx.x) * 4;
    if (i >= n) return;
    float4 v = *(const float4*)(x + i);
    float vv[4] = {v.x, v.y, v.z, v.w};
    __nv_bfloat16 hh[4], ll[4];
    #pragma unroll
    for (int j = 0; j < 4; j++) {
        hh[j] = __float2bfloat16(vv[j]);
        ll[j] = __float2bfloat16(vv[j] - __bfloat162float(hh[j]));
    }
    *(__nv_bfloat162*)(h + i)     = __nv_bfloat162(hh[0], hh[1]);
    *(__nv_bfloat162*)(h + i + 2) = __nv_bfloat162(hh[2], hh[3]);
    *(__nv_bfloat162*)(l + i)     = __nv_bfloat162(ll[0], ll[1]);
    *(__nv_bfloat162*)(l + i + 2) = __nv_bfloat162(ll[2], ll[3]);
}

// Split + transpose: W fp32 [K][N] -> H,L bf16 [N][K]
__global__ void splitT_kernel(const float* __restrict__ W,
                              __nv_bfloat16* __restrict__ H,
                              __nv_bfloat16* __restrict__ Lo, int K, int N)
{
    __shared__ float t[32][33];
    int n0 = blockIdx.x * 32, k0 = blockIdx.y * 32;
    int tx = threadIdx.x, ty = threadIdx.y;
    #pragma unroll
    for (int r = ty; r < 32; r += 8)
        t[r][tx] = W[(size_t)(k0 + r) * N + n0 + tx];
    __syncthreads();
    #pragma unroll
    for (int r = ty; r < 32; r += 8) {
        float v = t[tx][r];
        __nv_bfloat16 h = __float2bfloat16(v);
        __nv_bfloat16 l = __float2bfloat16(v - __bfloat162float(h));
        H[(size_t)(n0 + r) * K + k0 + tx]  = h;
        Lo[(size_t)(n0 + r) * K + k0 + tx] = l;
    }
}

// ---------------------------------------------------------------------------
// bf16x3 GEMM on mma.sync: C[M,N] = (Ah+Al)[M,K] @ (Bh+Bl)^T[N,K], fp32 out.
// Block 128x128, BK=64, 8 warps (2M x 4N), warp tile 64x32.
// smem stride 72 halves (conflict-free ldmatrix). 2-stage cp.async pipeline.
// ---------------------------------------------------------------------------
#define GST  72
#define GBUF (128*GST)   // halves per stage per array

__global__ __launch_bounds__(256, 1) void gemm_bf3(
    const __nv_bfloat16* __restrict__ Ah, const __nv_bfloat16* __restrict__ Al,
    const __nv_bfloat16* __restrict__ Bh, const __nv_bfloat16* __restrict__ Bl,
    float* __restrict__ C, int M, int N, int K)
{
    extern __shared__ char dyn_smem[];
    __nv_bfloat16* smh = (__nv_bfloat16*)dyn_smem;
    const uint32_t sb = smem_u32(smh);
    const int tid = threadIdx.x, lane = tid & 31, wid = tid >> 5;
    const int wm = (wid & 1) * 64, wn = (wid >> 1) * 32;
    const int lrow = lane & 15, lcol = (lane >> 4) * 8;
    const int m0 = blockIdx.y * 128, n0 = blockIdx.x * 128;

    const __nv_bfloat16* gAh = Ah + (size_t)m0 * K;
    const __nv_bfloat16* gAl = Al + (size_t)m0 * K;
    const __nv_bfloat16* gBh = Bh + (size_t)n0 * K;
    const __nv_bfloat16* gBl = Bl + (size_t)n0 * K;

    float acc[4][4][4] = {};
    const int nit = K / 64;

    auto load_stage = [&](int it) {
        const int s = it & 1;
        const int k0 = it * 64;
        for (int i = tid; i < 1024; i += 256) {
            int row = i >> 3, c = i & 7;
            uint32_t so = (uint32_t)(row * GST + c * 8);
            size_t go = (size_t)row * K + k0 + c * 8;
            cp16(smh + (0 * 2 + s) * GBUF + so, gAh + go);
            cp16(smh + (1 * 2 + s) * GBUF + so, gAl + go);
            cp16(smh + (2 * 2 + s) * GBUF + so, gBh + go);
            cp16(smh + (3 * 2 + s) * GBUF + so, gBl + go);
        }
        CP_COMMIT();
    };

    load_stage(0);

    for (int it = 0; it < nit; it++) {
        const int s = it & 1;
        if (it + 1 < nit) { load_stage(it + 1); CP_WAIT1(); }
        else              { CP_WAIT0(); }
        __syncthreads();

        const uint32_t aH = sb + (uint32_t)((0 * 2 + s) * GBUF) * 2;
        const uint32_t aL = sb + (uint32_t)((1 * 2 + s) * GBUF) * 2;
        const uint32_t bH = sb + (uint32_t)((2 * 2 + s) * GBUF) * 2;
        const uint32_t bL = sb + (uint32_t)((3 * 2 + s) * GBUF) * 2;

        #pragma unroll
        for (int ks = 0; ks < 4; ks++) {
            uint32_t ah[4][4], al[4][4], bh[4][2], bl[4][2];
            #pragma unroll
            for (int mi = 0; mi < 4; mi++) {
                uint32_t off = (uint32_t)((wm + mi * 16 + lrow) * GST + ks * 16 + lcol) * 2;
                ldsm4(ah[mi], aH + off);
                ldsm4(al[mi], aL + off);
            }
            #pragma unroll
            for (int nh = 0; nh < 2; nh++) {
                uint32_t off = (uint32_t)((wn + nh * 16 + lrow) * GST + ks * 16 + lcol) * 2;
                uint32_t r[4], q[4];
                ldsm4(r, bH + off);
                ldsm4(q, bL + off);
                bh[nh*2][0] = r[0]; bh[nh*2][1] = r[2];
                bh[nh*2+1][0] = r[1]; bh[nh*2+1][1] = r[3];
                bl[nh*2][0] = q[0]; bl[nh*2][1] = q[2];
                bl[nh*2+1][0] = q[1]; bl[nh*2+1][1] = q[3];
            }
            #pragma unroll
            for (int mi = 0; mi < 4; mi++)
                #pragma unroll
                for (int nj = 0; nj < 4; nj++) {
                    mma_bf16(acc[mi][nj], ah[mi], bh[nj]);
                    mma_bf16(acc[mi][nj], ah[mi], bl[nj]);
                    mma_bf16(acc[mi][nj], al[mi], bh[nj]);
                }
        }
        __syncthreads();
    }

    // Epilogue
    const int g = lane >> 2;
    #pragma unroll
    for (int mi = 0; mi < 4; mi++) {
        #pragma unroll
        for (int nj = 0; nj < 4; nj++) {
            int row = m0 + wm + mi * 16 + g;
            int col = n0 + wn + nj * 8 + 2 * (lane & 3);
            *(float2*)&C[(size_t)row * N + col] =
                make_float2(acc[mi][nj][0], acc[mi][nj][1]);
            *(float2*)&C[(size_t)(row + 8) * N + col] =
                make_float2(acc[mi][nj][2], acc[mi][nj][3]);
        }
    }
}

// ---------------------------------------------------------------------------
// RoPE kernels (interleaved rotation, concat-layout angles)
// ---------------------------------------------------------------------------
__global__ void rope_q_kernel(const float* __restrict__ q, __half* __restrict__ qh)
{
    long idx = (long)blockIdx.x * blockDim.x + threadIdx.x;  // L*NH*64 pairs
    if (idx >= (long)L * NH * 64) return;
    int  p  = (int)(idx & 63);
    long th = idx >> 6;                 // t*NH + h
    int  t  = (int)(th >> 5);

    const float Cc = 0.14391156644565413f; // ln(10000)/64
    int j0 = 2 * p, j1 = 2 * p + 1;
    float a0 = (float)t * expf(-Cc * (float)(j0 & 63));
    float a1 = (float)t * expf(-Cc * (float)(j1 & 63));
    float c0, s0, c1, s1;
    sincosf(a0, &s0, &c0);
    sincosf(a1, &s1, &c1);

    const float* base = q + th * 128;
    float x0 = base[j0], x1 = base[j1];
    float y0 = (x0 * c0 - x1 * s0) * ATT_SCALE;
    float y1 = (x1 * c1 + x0 * s1) * ATT_SCALE;
    *(__half2*)(qh + th * 128 + j0) = __floats2half2_rn(y0, y1);
}

__global__ void rope_k_kernel(float* __restrict__ kv, __half* __restrict__ kh)
{
    long idx = (long)blockIdx.x * blockDim.x + threadIdx.x;  // L*NKV*64 pairs
    if (idx >= (long)L * NKV * 64) return;
    int  p  = (int)(idx & 63);
    long th = idx >> 6;                 // t*NKV + hk
    int  t  = (int)(th >> 3);
    int  hk = (int)(th & 7);

    const float Cc = 0.14391156644565413f;
    int j0 = 2 * p, j1 = 2 * p + 1;
    float a0 = (float)t * expf(-Cc * (float)(j0 & 63));
    float a1 = (float)t * expf(-Cc * (float)(j1 & 63));
    float c0, s0, c1, s1;
    sincosf(a0, &s0, &c0);
    sincosf(a1, &s1, &c1);

    float* base = kv + (size_t)t * 2048 + hk * 128;
    float x0 = base[j0], x1 = base[j1];
    float y0 = x0 * c0 - x1 * s0;
    float y1 = x1 * c1 + x0 * s1;
    base[j0] = y0;
    base[j1] = y1;
    *(__half2*)(kh + (size_t)t * KVDIM + hk * 128 + j0) = __floats2half2_rn(y0, y1);
}

__global__ void conv_vh_kernel(const float* __restrict__ kv, __half* __restrict__ vh)
{
    long idx = ((long)blockIdx.x * blockDim.x + threadIdx.x) * 2;
    if (idx >= (long)L * KVDIM) return;
    int t = (int)(idx >> 10), j = (int)(idx & 1023);
    float2 v = *(const float2*)(kv + (size_t)t * 2048 + 1024 + j);
    *(__half2*)(vh + idx) = __floats2half2_rn(v.x, v.y);
}

__global__ void write_kv_kernel(const float* __restrict__ kv,
                                float* __restrict__ ok, float* __restrict__ ov)
{
    long idx = (long)blockIdx.x * blockDim.x + threadIdx.x;
    const long total = (long)NH * L * HD;
    if (idx >= total) return;
    int h = (int)(idx >> 18);
    int rem = (int)(idx & 262143);
    int t = rem >> 7;
    int d = rem & 127;
    long src = (long)t * 2048 + (h >> 2) * HD + d;
    ok[idx] = kv[src];
    ov[idx] = kv[src + 1024];
}

// ---------------------------------------------------------------------------
// Flash attention on mma.sync fp16. Block: head x 128-row Q tile, 256 threads.
// Warp = 16 Q rows. 64-key steps, double-buffered cp.async K/V fp16 tiles.
// P stays in registers (S-frag -> PV A-frag identity mapping).
// ---------------------------------------------------------------------------
#define QS_ST 136
#define KV_ST 136
#define KOFF  (128*QS_ST)            // halves
#define VOFF  (KOFF + 2*64*KV_ST)
#define ATT_SMEM ((KOFF + 4*64*KV_ST) * 2)   // bytes = 104448

__global__ __launch_bounds__(256, 1) void attn_mma(
    const __half* __restrict__ qh, const __half* __restrict__ kh,
    const __half* __restrict__ vh, float* __restrict__ o)
{
    extern __shared__ char dyn_smem[];
    __half* smh = (__half*)dyn_smem;
    const uint32_t sb = smem_u32(smh);
    const int tid = threadIdx.x, lane = tid & 31, wid = tid >> 5;
    const int h = blockIdx.y, qt = blockIdx.x, kvh = h >> 2;
    const int g = lane >> 2;
    const int lrow = lane & 15, lcol = (lane >> 4) * 8;

    // Stage Q tile (128 x 128 halves) and load resident Q fragments
    for (int i = tid; i < 2048; i += 256) {
        int r = i >> 4, c = i & 15;
        cp16(smh + r * QS_ST + c * 8,
             qh + (size_t)(qt * 128 + r) * QDIM + h * HD + c * 8);
    }
    CP_COMMIT(); CP_WAIT0();
    __syncthreads();
    uint32_t aQ[8][4];
    #pragma unroll
    for (int ks = 0; ks < 8; ks++)
        ldsm4(aQ[ks], sb + (uint32_t)((wid * 16 + lrow) * QS_ST + ks * 16 + lcol) * 2);

    auto load_kv = [&](int kt) {
        const int s = kt & 1;
        const __half* kg = kh + (size_t)(kt * 64) * KVDIM + kvh * HD;
        const __half* vg = vh + (size_t)(kt * 64) * KVDIM + kvh * HD;
        __half* ksm = smh + KOFF + s * (64 * KV_ST);
        __half* vsm = smh + VOFF + s * (64 * KV_ST);
        for (int i = tid; i < 1024; i += 256) {
            int r = i >> 4, c = i & 15;
            cp16(ksm + r * KV_ST + c * 8, kg + (size_t)r * KVDIM + c * 8);
            cp16(vsm + r * KV_ST + c * 8, vg + (size_t)r * KVDIM + c * 8);
        }
        CP_COMMIT();
    };

    float O[16][4] = {};
    float m0 = -1e30f, m1 = -1e30f, l0 = 0.f, l1 = 0.f;

    load_kv(0);

    for (int kt = 0; kt < 32; kt++) {
        if (kt + 1 < 32) { load_kv(kt + 1); CP_WAIT1(); }
        else             { CP_WAIT0(); }
        __syncthreads();

        const uint32_t kbase = sb + (uint32_t)(KOFF + (kt & 1) * (64 * KV_ST)) * 2;
        const uint32_t vbase = sb + (uint32_t)(VOFF + (kt & 1) * (64 * KV_ST)) * 2;

        // S = Q @ K^T  (m16 x n64 per warp)
        float c[8][4] = {};
        #pragma unroll
        for (int ks = 0; ks < 8; ks++) {
            #pragma unroll
            for (int nh = 0; nh < 4; nh++) {
                uint32_t r[4];
                ldsm4(r, kbase + (uint32_t)((nh * 16 + lrow) * KV_ST + ks * 16 + lcol) * 2);
                uint32_t b0[2] = {r[0], r[2]};
                uint32_t b1[2] = {r[1], r[3]};
                mma_f16(c[nh * 2],     aQ[ks], b0);
                mma_f16(c[nh * 2 + 1], aQ[ks], b1);
            }
        }

        // Online softmax (rows g and g+8)
        float mx0 = m0, mx1 = m1;
        #pragma unroll
        for (int t = 0; t < 8; t++) {
            mx0 = fmaxf(mx0, fmaxf(c[t][0], c[t][1]));
            mx1 = fmaxf(mx1, fmaxf(c[t][2], c[t][3]));
        }
        mx0 = fmaxf(mx0, __shfl_xor_sync(0xFFFFFFFF, mx0, 1));
        mx0 = fmaxf(mx0, __shfl_xor_sync(0xFFFFFFFF, mx0, 2));
        mx1 = fmaxf(mx1, __shfl_xor_sync(0xFFFFFFFF, mx1, 1));
        mx1 = fmaxf(mx1, __shfl_xor_sync(0xFFFFFFFF, mx1, 2));
        float f0 = __expf(m0 - mx0), f1 = __expf(m1 - mx1);
        m0 = mx0; m1 = mx1;
        float s0 = 0.f, s1 = 0.f;
        #pragma unroll
        for (int t = 0; t < 8; t++) {
            c[t][0] = __expf(c[t][0] - m0); s0 += c[t][0];
            c[t][1] = __expf(c[t][1] - m0); s0 += c[t][1];
            c[t][2] = __expf(c[t][2] - m1); s1 += c[t][2];
            c[t][3] = __expf(c[t][3] - m1); s1 += c[t][3];
        }
        s0 += __shfl_xor_sync(0xFFFFFFFF, s0, 1);
        s0 += __shfl_xor_sync(0xFFFFFFFF, s0, 2);
        s1 += __shfl_xor_sync(0xFFFFFFFF, s1, 1);
        s1 += __shfl_xor_sync(0xFFFFFFFF, s1, 2);
        l0 = l0 * f0 + s0;
        l1 = l1 * f1 + s1;

        #pragma unroll
        for (int t = 0; t < 16; t++) {
            O[t][0] *= f0; O[t][1] *= f0;
            O[t][2] *= f1; O[t][3] *= f1;
        }

        // O += P @ V  (P from register S-frags)
        #pragma unroll
        for (int k2 = 0; k2 < 4; k2++) {
            uint32_t a[4];
            a[0] = pack_h2(c[2 * k2][0],     c[2 * k2][1]);
            a[1] = pack_h2(c[2 * k2][2],     c[2 * k2][3]);
            a[2] = pack_h2(c[2 * k2 + 1][0], c[2 * k2 + 1][1]);
            a[3] = pack_h2(c[2 * k2 + 1][2], c[2 * k2 + 1][3]);
            #pragma unroll
            for (int dj = 0; dj < 8; dj++) {
                uint32_t r[4];
                ldsm4t(r, vbase + (uint32_t)((k2 * 16 + lrow) * KV_ST + dj * 16 + lcol) * 2);
                uint32_t b0[2] = {r[0], r[1]};
                uint32_t b1[2] = {r[2], r[3]};
                mma_f16(O[dj * 2],     a, b0);
                mma_f16(O[dj * 2 + 1], a, b1);
            }
        }
        __syncthreads();
    }

    // Epilogue
    float inv0 = 1.f / l0, inv1 = 1.f / l1;
    const int row0 = qt * 128 + wid * 16 + g;
    #pragma unroll
    for (int t = 0; t < 16; t++) {
        float* d0 = o + (size_t)row0 * QDIM + h * HD + t * 8 + 2 * (lane & 3);
        float* d1 = o + (size_t)(row0 + 8) * QDIM + h * HD + t * 8 + 2 * (lane & 3);
        *(float2*)d0 = make_float2(O[t][0] * inv0, O[t][1] * inv0);
        *(float2*)d1 = make_float2(O[t][2] * inv1, O[t][3] * inv1);
    }
}

// ---------------------------------------------------------------------------
// Launch
// ---------------------------------------------------------------------------
extern "C" void kernel_launch(void* const* d_in, const int* in_sizes, int n_in,
                              void* d_out, int out_size)
{
    const float* x  = (const float*)d_in[0];
    const float* wq = (const float*)d_in[1];
    const float* wk = (const float*)d_in[2];
    const float* wv = (const float*)d_in[3];
    const float* wo = (const float*)d_in[4];
    float* out = (float*)d_out;

    float *pq, *pkv, *pattn;
    __half *pqh, *pkh, *pvh;
    __nv_bfloat16 *pxh, *pxl, *pah, *pal, *pwqh, *pwql, *pkvh, *pkvl, *pwoh, *pwol;
    cudaGetSymbolAddress((void**)&pq,   g_q);
    cudaGetSymbolAddress((void**)&pkv,  g_kv);
    cudaGetSymbolAddress((void**)&pattn,g_attn);
    cudaGetSymbolAddress((void**)&pqh,  g_qh);
    cudaGetSymbolAddress((void**)&pkh,  g_kh);
    cudaGetSymbolAddress((void**)&pvh,  g_vh);
    cudaGetSymbolAddress((void**)&pxh,  g_xh);
    cudaGetSymbolAddress((void**)&pxl,  g_xl);
    cudaGetSymbolAddress((void**)&pah,  g_ah);
    cudaGetSymbolAddress((void**)&pal,  g_al);
    cudaGetSymbolAddress((void**)&pwqh, g_wqh);
    cudaGetSymbolAddress((void**)&pwql, g_wql);
    cudaGetSymbolAddress((void**)&pkvh, g_kvh);
    cudaGetSymbolAddress((void**)&pkvl, g_kvl);
    cudaGetSymbolAddress((void**)&pwoh, g_woh);
    cudaGetSymbolAddress((void**)&pwol, g_wol);

    const int gemm_smem = 8 * GBUF * 2;   // 147456 B
    cudaFuncSetAttribute(gemm_bf3, cudaFuncAttributeMaxDynamicSharedMemorySize, gemm_smem);
    cudaFuncSetAttribute(attn_mma, cudaFuncAttributeMaxDynamicSharedMemorySize, ATT_SMEM);

    // 1) Splits
    {
        long nx = (long)L * DIM;
        split_kernel<<<(unsigned)(nx / (256 * 4)), 256>>>(x, pxh, pxl, nx);
        dim3 thr(32, 8);
        splitT_kernel<<<dim3(QDIM / 32, DIM / 32), thr>>>(wq, pwqh, pwql, DIM, QDIM);
        splitT_kernel<<<dim3(KVDIM / 32, DIM / 32), thr>>>(wk, pkvh, pkvl, DIM, KVDIM);
        splitT_kernel<<<dim3(KVDIM / 32, DIM / 32), thr>>>(wv, pkvh + (size_t)KVDIM * DIM,
                                                           pkvl + (size_t)KVDIM * DIM, DIM, KVDIM);
        splitT_kernel<<<dim3(DIM / 32, QDIM / 32), thr>>>(wo, pwoh, pwol, QDIM, DIM);
    }

    // 2) Projections: q = x@wq ; kv = x@(wk|wv)
    gemm_bf3<<<dim3(QDIM / 128, L / 128), 256, gemm_smem>>>(pxh, pxl, pwqh, pwql, pq, L, QDIM, DIM);
    gemm_bf3<<<dim3(2 * KVDIM / 128, L / 128), 256, gemm_smem>>>(pxh, pxl, pkvh, pkvl, pkv, L, 2 * KVDIM, DIM);

    // 3) RoPE + fp16 conversions
    {
        long pq_pairs = (long)L * NH * 64;
        long pk_pairs = (long)L * NKV * 64;
        rope_q_kernel<<<(unsigned)((pq_pairs + 255) / 256), 256>>>(pq, pqh);
        rope_k_kernel<<<(unsigned)((pk_pairs + 255) / 256), 256>>>(pkv, pkh);
        long nv = (long)L * KVDIM / 2;
        conv_vh_kernel<<<(unsigned)((nv + 255) / 256), 256>>>(pkv, pvh);
    }

    // 4) Emit repeated (k, v) output sections
    const long OUT0 = (long)L * QDIM;
    const long KVSZ = (long)NH * L * HD;
    if ((long)out_size >= OUT0 + 2 * KVSZ) {
        write_kv_kernel<<<(unsigned)((KVSZ + 255) / 256), 256>>>(pkv, out + OUT0, out + OUT0 + KVSZ);
    }

    // 5) Flash attention (fp16 mma)
    attn_mma<<<dim3(L / 128, NH), 256, ATT_SMEM>>>(pqh, pkh, pvh, pattn);

    // 6) Split attention output, final projection
    {
        long na = (long)L * QDIM;
        split_kernel<<<(unsigned)(na / (256 * 4)), 256>>>(pattn, pah, pal, na);
    }
    gemm_bf3<<<dim3(DIM / 128, L / 128), 256, gemm_smem>>>(pah, pal, pwoh, pwol, out, L, DIM, DIM);
}